// round 1
// baseline (speedup 1.0000x reference)
#include <cuda_runtime.h>

// Problem constants (fixed by reference: x [8,2048,1024], W [1024,1024])
#define DIMD  1024
#define BATCH 8
#define SEQ   2048

// Scratch (static device memory — no allocations)
__device__ float g_V[(size_t)BATCH * SEQ * DIMD];            // 64 MB, V == Q
__device__ float g_K[(size_t)BATCH * SEQ * DIMD];            // 64 MB
__device__ float g_S[(size_t)BATCH * SEQ * SEQ];             // 128 MB scores/attn

// ---------------------------------------------------------------------------
// Tiled SGEMM, C = alpha * A @ B^T (+bias), A:[M,K] rm, B:[N,K] rm, C:[M,N] rm
// BM=BN=128, BK=16, 8x8 per thread, 256 threads.
// All dims assumed multiples of tile sizes (true for this problem).
// ---------------------------------------------------------------------------
#define BM 128
#define BN 128
#define BK 16
#define TM 8
#define TN 8

__global__ __launch_bounds__(256, 2)
void sgemm_nt(const float* __restrict__ A, const float* __restrict__ B,
              const float* __restrict__ bias, float* __restrict__ C,
              int M, int N, int K, float alpha,
              long long strideA, long long strideB, long long strideC)
{
    const int bz = blockIdx.z;
    A += (long long)bz * strideA;
    B += (long long)bz * strideB;
    C += (long long)bz * strideC;

    const int tile_m = blockIdx.y * BM;
    const int tile_n = blockIdx.x * BN;

    __shared__ float As[BK][BM];
    __shared__ float Bs[BK][BN];

    const int tid = threadIdx.x;
    // loaders: 128 rows x 16 cols per tile, float4 per thread x2
    const int lr = tid >> 2;          // 0..63
    const int lc = (tid & 3) << 2;    // 0,4,8,12

    const int tx = (tid & 15) * TN;   // 0..120
    const int ty = (tid >> 4) * TM;   // 0..120

    float acc[TM][TN] = {};

    for (int k0 = 0; k0 < K; k0 += BK) {
        #pragma unroll
        for (int i = 0; i < 2; i++) {
            const int r = lr + i * 64;
            float4 a = *(const float4*)(A + (long long)(tile_m + r) * K + k0 + lc);
            As[lc + 0][r] = a.x; As[lc + 1][r] = a.y;
            As[lc + 2][r] = a.z; As[lc + 3][r] = a.w;
            float4 b = *(const float4*)(B + (long long)(tile_n + r) * K + k0 + lc);
            Bs[lc + 0][r] = b.x; Bs[lc + 1][r] = b.y;
            Bs[lc + 2][r] = b.z; Bs[lc + 3][r] = b.w;
        }
        __syncthreads();

        #pragma unroll
        for (int k = 0; k < BK; k++) {
            float ra[TM], rb[TN];
            #pragma unroll
            for (int i = 0; i < TM; i++) ra[i] = As[k][ty + i];
            #pragma unroll
            for (int j = 0; j < TN; j++) rb[j] = Bs[k][tx + j];
            #pragma unroll
            for (int i = 0; i < TM; i++)
                #pragma unroll
                for (int j = 0; j < TN; j++)
                    acc[i][j] += ra[i] * rb[j];
        }
        __syncthreads();
    }

    #pragma unroll
    for (int i = 0; i < TM; i++) {
        float* crow = C + (long long)(tile_m + ty + i) * N + tile_n + tx;
        #pragma unroll
        for (int j = 0; j < TN; j += 4) {
            float4 v;
            v.x = alpha * acc[i][j + 0];
            v.y = alpha * acc[i][j + 1];
            v.z = alpha * acc[i][j + 2];
            v.w = alpha * acc[i][j + 3];
            if (bias) {
                v.x += bias[tile_n + tx + j + 0];
                v.y += bias[tile_n + tx + j + 1];
                v.z += bias[tile_n + tx + j + 2];
                v.w += bias[tile_n + tx + j + 3];
            }
            *(float4*)(crow + j) = v;
        }
    }
}

// ---------------------------------------------------------------------------
// Tiled SGEMM, C = A @ B, A:[M,K] rm, B:[K,N] rm, C:[M,N] rm
// ---------------------------------------------------------------------------
__global__ __launch_bounds__(256, 2)
void sgemm_nn(const float* __restrict__ A, const float* __restrict__ B,
              float* __restrict__ C,
              int M, int N, int K,
              long long strideA, long long strideB, long long strideC)
{
    const int bz = blockIdx.z;
    A += (long long)bz * strideA;
    B += (long long)bz * strideB;
    C += (long long)bz * strideC;

    const int tile_m = blockIdx.y * BM;
    const int tile_n = blockIdx.x * BN;

    __shared__ float As[BK][BM];
    __shared__ float Bs[BK][BN];

    const int tid = threadIdx.x;
    // A loader (same as NT): 128 rows x 16 cols
    const int lr = tid >> 2;
    const int lc = (tid & 3) << 2;
    // B loader: 16 rows x 128 cols
    const int br = tid >> 5;          // 0..7
    const int bc = (tid & 31) << 2;   // 0..124

    const int tx = (tid & 15) * TN;
    const int ty = (tid >> 4) * TM;

    float acc[TM][TN] = {};

    for (int k0 = 0; k0 < K; k0 += BK) {
        #pragma unroll
        for (int i = 0; i < 2; i++) {
            const int r = lr + i * 64;
            float4 a = *(const float4*)(A + (long long)(tile_m + r) * K + k0 + lc);
            As[lc + 0][r] = a.x; As[lc + 1][r] = a.y;
            As[lc + 2][r] = a.z; As[lc + 3][r] = a.w;

            const int kr = br + i * 8;
            float4 b = *(const float4*)(B + (long long)(k0 + kr) * N + tile_n + bc);
            *(float4*)&Bs[kr][bc] = b;
        }
        __syncthreads();

        #pragma unroll
        for (int k = 0; k < BK; k++) {
            float ra[TM], rb[TN];
            #pragma unroll
            for (int i = 0; i < TM; i++) ra[i] = As[k][ty + i];
            #pragma unroll
            for (int j = 0; j < TN; j++) rb[j] = Bs[k][tx + j];
            #pragma unroll
            for (int i = 0; i < TM; i++)
                #pragma unroll
                for (int j = 0; j < TN; j++)
                    acc[i][j] += ra[i] * rb[j];
        }
        __syncthreads();
    }

    #pragma unroll
    for (int i = 0; i < TM; i++) {
        float* crow = C + (long long)(tile_m + ty + i) * N + tile_n + tx;
        #pragma unroll
        for (int j = 0; j < TN; j += 4) {
            float4 v;
            v.x = acc[i][j + 0];
            v.y = acc[i][j + 1];
            v.z = acc[i][j + 2];
            v.w = acc[i][j + 3];
            *(float4*)(crow + j) = v;
        }
    }
}

// ---------------------------------------------------------------------------
// Row softmax, in place. One block (256 threads) per row of length SEQ (2048).
// Each thread owns 8 elements, kept in registers between passes.
// ---------------------------------------------------------------------------
__global__ __launch_bounds__(256)
void softmax_rows(float* __restrict__ S)
{
    const long long row = blockIdx.x;
    float* p = S + row * (long long)SEQ;
    const int tid = threadIdx.x;
    const int lane = tid & 31;
    const int warp = tid >> 5;

    __shared__ float red_max[8];
    __shared__ float red_sum[8];

    float v[8];
    float m = -1e30f;
    #pragma unroll
    for (int i = 0; i < 8; i++) {
        v[i] = p[tid + i * 256];
        m = fmaxf(m, v[i]);
    }
    #pragma unroll
    for (int o = 16; o > 0; o >>= 1) m = fmaxf(m, __shfl_xor_sync(0xffffffffu, m, o));
    if (lane == 0) red_max[warp] = m;
    __syncthreads();
    float mall = red_max[0];
    #pragma unroll
    for (int w = 1; w < 8; w++) mall = fmaxf(mall, red_max[w]);

    float s = 0.0f;
    #pragma unroll
    for (int i = 0; i < 8; i++) {
        v[i] = __expf(v[i] - mall);
        s += v[i];
    }
    #pragma unroll
    for (int o = 16; o > 0; o >>= 1) s += __shfl_xor_sync(0xffffffffu, s, o);
    if (lane == 0) red_sum[warp] = s;
    __syncthreads();
    float sall = 0.0f;
    #pragma unroll
    for (int w = 0; w < 8; w++) sall += red_sum[w];

    const float inv = __frcp_rn(sall);
    #pragma unroll
    for (int i = 0; i < 8; i++) p[tid + i * 256] = v[i] * inv;
}

// ---------------------------------------------------------------------------
// Launch
// ---------------------------------------------------------------------------
extern "C" void kernel_launch(void* const* d_in, const int* in_sizes, int n_in,
                              void* d_out, int out_size)
{
    const float* x  = (const float*)d_in[0];
    const float* W1 = (const float*)d_in[1];
    const float* b1 = (const float*)d_in[2];
    const float* W2 = (const float*)d_in[3];
    const float* b2 = (const float*)d_in[4];
    float* out = (float*)d_out;

    float *pV, *pK, *pS;
    cudaGetSymbolAddress((void**)&pV, g_V);
    cudaGetSymbolAddress((void**)&pK, g_K);
    cudaGetSymbolAddress((void**)&pS, g_S);

    const int M_lin = BATCH * SEQ;     // 16384
    dim3 blk(256);

    // V (== Q) = x @ W1^T + b1 : [16384,1024]
    sgemm_nt<<<dim3(DIMD / BN, M_lin / BM, 1), blk>>>(
        x, W1, b1, pV, M_lin, DIMD, DIMD, 1.0f, 0, 0, 0);

    // K = x @ W2^T + b2 : [16384,1024]
    sgemm_nt<<<dim3(DIMD / BN, M_lin / BM, 1), blk>>>(
        x, W2, b2, pK, M_lin, DIMD, DIMD, 1.0f, 0, 0, 0);

    // scores[b,k,q] = scale * K[b,k,:] . V[b,q,:]   (Q == V)
    const float scale = 1.0f / 32.0f;  // 1/sqrt(1024)
    sgemm_nt<<<dim3(SEQ / BN, SEQ / BM, BATCH), blk>>>(
        pK, pV, nullptr, pS, SEQ, SEQ, DIMD, scale,
        (long long)SEQ * DIMD, (long long)SEQ * DIMD, (long long)SEQ * SEQ);

    // softmax over q (last axis), in place
    softmax_rows<<<BATCH * SEQ, 256>>>(pS);

    // out[b,k,d] = attn[b,k,:] @ V[b,:,d]
    sgemm_nn<<<dim3(DIMD / BN, SEQ / BM, BATCH), blk>>>(
        pS, pV, out, SEQ, DIMD, SEQ,
        (long long)SEQ * SEQ, (long long)SEQ * DIMD, (long long)SEQ * DIMD);
}

// round 3
// speedup vs baseline: 7.0485x; 7.0485x over previous
#include <cuda_runtime.h>
#include <cuda_fp16.h>
#include <cstdint>

#define DIMD  1024
#define BATCH 8
#define SEQ   2048

// ---------------------------------------------------------------------------
// Scratch (static device memory — no allocations)
// ---------------------------------------------------------------------------
__device__ __half g_xh [(size_t)BATCH * SEQ * DIMD];   // x in fp16
__device__ __half g_W1h[(size_t)DIMD * DIMD];
__device__ __half g_W2h[(size_t)DIMD * DIMD];
__device__ __half g_Vh [(size_t)BATCH * SEQ * DIMD];   // V fp16 (== Q)
__device__ __half g_Kh [(size_t)BATCH * SEQ * DIMD];   // K fp16
__device__ __half g_VTh[(size_t)BATCH * SEQ * DIMD];   // V^T fp16 [B,D,S]
__device__ float  g_S  [(size_t)BATCH * SEQ * SEQ];    // scores fp32
__device__ __half g_Ph [(size_t)BATCH * SEQ * SEQ];    // probs fp16

// ---------------------------------------------------------------------------
// Helpers
// ---------------------------------------------------------------------------
__device__ __forceinline__ uint32_t smem_u32(const void* p) {
    return (uint32_t)__cvta_generic_to_shared(p);
}
__device__ __forceinline__ uint32_t swz(uint32_t o) { return o ^ ((o >> 3) & 0x70); }

__device__ __forceinline__ void cp_async16(uint32_t dst, const void* src) {
    asm volatile("cp.async.cg.shared.global [%0], [%1], 16;" :: "r"(dst), "l"(src));
}
__device__ __forceinline__ void cp_commit() {
    asm volatile("cp.async.commit_group;" ::: "memory");
}
__device__ __forceinline__ void cp_wait1() {
    asm volatile("cp.async.wait_group 1;" ::: "memory");
}
__device__ __forceinline__ void cp_wait0() {
    asm volatile("cp.async.wait_group 0;" ::: "memory");
}
__device__ __forceinline__ void ldsm_x4(uint32_t* r, uint32_t addr) {
    asm volatile("ldmatrix.sync.aligned.m8n8.x4.shared.b16 {%0,%1,%2,%3}, [%4];"
                 : "=r"(r[0]), "=r"(r[1]), "=r"(r[2]), "=r"(r[3]) : "r"(addr));
}
__device__ __forceinline__ void mma16816(float* c, const uint32_t* a,
                                         uint32_t b0, uint32_t b1) {
    asm volatile("mma.sync.aligned.m16n8k16.row.col.f32.f16.f16.f32 "
                 "{%0,%1,%2,%3}, {%4,%5,%6,%7}, {%8,%9}, {%0,%1,%2,%3};"
                 : "+f"(c[0]), "+f"(c[1]), "+f"(c[2]), "+f"(c[3])
                 : "r"(a[0]), "r"(a[1]), "r"(a[2]), "r"(a[3]), "r"(b0), "r"(b1));
}

// ---------------------------------------------------------------------------
// fp16 tensor-core GEMM: C[M,N] = alpha * A[M,K] @ B[N,K]^T (+bias)  (NT)
// Tile 128x128, K-chunk 64 halfs, 3-stage cp.async pipeline, 8 warps,
// warp tile 64x32 (4x4 m16n8k16 mmas).
// mode 0: half output + bias.  mode 1: float output, no bias.
// ---------------------------------------------------------------------------
#define BM 128
#define BN 128
#define BKH 64
#define STG 32768          // (128 + 128) rows * 128 bytes
#define NSTAGE 3

__global__ __launch_bounds__(256, 2)
void mm_h16(const __half* __restrict__ A, const __half* __restrict__ B,
            const float* __restrict__ bias, void* __restrict__ Cout,
            int M, int N, int K, float alpha, int mode,
            long long sA, long long sB, long long sC)
{
    extern __shared__ char smem[];
    const uint32_t sbase = smem_u32(smem);
    const int tid = threadIdx.x;
    const int wid = tid >> 5;
    const int lane = tid & 31;

    const int bz = blockIdx.z;
    A += (long long)bz * sA;
    B += (long long)bz * sB;

    const int tile_m = blockIdx.y * BM;
    const int tile_n = blockIdx.x * BN;
    const int T = K / BKH;

    // --- loader plan: 2048 16B chunks per stage, 8 per thread ---
    const int ch = tid & 7;            // k-chunk within row (16B units)
    const int rb = tid >> 3;           // base row 0..31
    const __half* gA = A + (size_t)(tile_m + rb) * K + ch * 8;
    const __half* gB = B + (size_t)(tile_n + rb) * K + ch * 8;
    const uint32_t dA = swz((uint32_t)(rb * 128 + ch * 16));

#define LOAD_STAGE(s, t) do { \
        uint32_t sb_ = sbase + (uint32_t)(s) * STG; \
        const __half* pa_ = gA + (size_t)(t) * BKH; \
        const __half* pb_ = gB + (size_t)(t) * BKH; \
        _Pragma("unroll") \
        for (int i_ = 0; i_ < 4; i_++) \
            cp_async16(sb_ + dA + i_ * 4096, pa_ + (size_t)i_ * 32 * K); \
        _Pragma("unroll") \
        for (int i_ = 0; i_ < 4; i_++) \
            cp_async16(sb_ + 16384 + dA + i_ * 4096, pb_ + (size_t)i_ * 32 * K); \
        cp_commit(); \
    } while (0)

    LOAD_STAGE(0, 0);
    LOAD_STAGE(1, 1);

    // --- compute plan ---
    const int wm = wid & 1;            // 0..1  (64 rows each)
    const int wn = wid >> 1;           // 0..3  (32 cols each)
    const int lr = lane & 15;          // ldmatrix row
    const int lcb = (lane >> 4) * 16;  // ldmatrix col-half byte offset

    float acc[4][4][4] = {};

    for (int t = 0; t < T; t++) {
        if (t == T - 1) cp_wait0(); else cp_wait1();
        __syncthreads();

        const uint32_t sa = sbase + (uint32_t)(t % 3) * STG;
        const uint32_t sb = sa + 16384;

        #pragma unroll
        for (int ks = 0; ks < 4; ks++) {
            uint32_t a[4][4], b[2][4];
            #pragma unroll
            for (int mi = 0; mi < 4; mi++)
                ldsm_x4(a[mi], sa + swz((uint32_t)((wm * 64 + mi * 16 + lr) * 128
                                                   + ks * 32 + lcb)));
            #pragma unroll
            for (int nb = 0; nb < 2; nb++)
                ldsm_x4(b[nb], sb + swz((uint32_t)((wn * 32 + nb * 16 + lr) * 128
                                                   + ks * 32 + lcb)));
            #pragma unroll
            for (int mi = 0; mi < 4; mi++)
                #pragma unroll
                for (int ni = 0; ni < 4; ni++)
                    mma16816(acc[mi][ni], a[mi],
                             b[ni >> 1][ni & 1], b[ni >> 1][(ni & 1) + 2]);
        }

        if (t + 2 < T) LOAD_STAGE((t + 2) % 3, t + 2);
        __syncthreads();
    }

    // --- epilogue ---
    const int er = lane >> 2;          // 0..7
    const int ec = (lane & 3) * 2;     // 0,2,4,6

    if (mode == 0) {
        __half* C = (__half*)Cout + (long long)bz * sC;
        #pragma unroll
        for (int mi = 0; mi < 4; mi++) {
            #pragma unroll
            for (int ni = 0; ni < 4; ni++) {
                int m0 = tile_m + wm * 64 + mi * 16 + er;
                int n0 = tile_n + wn * 32 + ni * 8 + ec;
                float bx = bias[n0], by = bias[n0 + 1];
                float* c = acc[mi][ni];
                *(__half2*)(C + (size_t)m0 * N + n0) =
                    __floats2half2_rn(c[0] * alpha + bx, c[1] * alpha + by);
                *(__half2*)(C + (size_t)(m0 + 8) * N + n0) =
                    __floats2half2_rn(c[2] * alpha + bx, c[3] * alpha + by);
            }
        }
    } else {
        float* C = (float*)Cout + (long long)bz * sC;
        #pragma unroll
        for (int mi = 0; mi < 4; mi++) {
            #pragma unroll
            for (int ni = 0; ni < 4; ni++) {
                int m0 = tile_m + wm * 64 + mi * 16 + er;
                int n0 = tile_n + wn * 32 + ni * 8 + ec;
                float* c = acc[mi][ni];
                *(float2*)(C + (size_t)m0 * N + n0) =
                    make_float2(c[0] * alpha, c[1] * alpha);
                *(float2*)(C + (size_t)(m0 + 8) * N + n0) =
                    make_float2(c[2] * alpha, c[3] * alpha);
            }
        }
    }
#undef LOAD_STAGE
}

// ---------------------------------------------------------------------------
// fp32 -> fp16 conversion (vectorized)
// ---------------------------------------------------------------------------
__global__ __launch_bounds__(256)
void f2h(const float* __restrict__ in, __half* __restrict__ out, long long n4)
{
    long long i = (long long)blockIdx.x * blockDim.x + threadIdx.x;
    long long stride = (long long)gridDim.x * blockDim.x;
    for (; i < n4; i += stride) {
        float4 v = ((const float4*)in)[i];
        ((__half2*)out)[2 * i + 0] = __floats2half2_rn(v.x, v.y);
        ((__half2*)out)[2 * i + 1] = __floats2half2_rn(v.z, v.w);
    }
}

// ---------------------------------------------------------------------------
// Batched fp16 transpose: [B,S,D] -> [B,D,S]
// ---------------------------------------------------------------------------
__global__ __launch_bounds__(256)
void transpose_h(const __half* __restrict__ in, __half* __restrict__ out)
{
    __shared__ __half t[32][33];
    const int b = blockIdx.z;
    const __half* I = in + (size_t)b * SEQ * DIMD;
    __half* O = out + (size_t)b * SEQ * DIMD;
    const int d0 = blockIdx.x * 32, s0 = blockIdx.y * 32;
    #pragma unroll
    for (int i = threadIdx.y; i < 32; i += 8)
        t[i][threadIdx.x] = I[(size_t)(s0 + i) * DIMD + d0 + threadIdx.x];
    __syncthreads();
    #pragma unroll
    for (int i = threadIdx.y; i < 32; i += 8)
        O[(size_t)(d0 + i) * SEQ + s0 + threadIdx.x] = t[threadIdx.x][i];
}

// ---------------------------------------------------------------------------
// Row softmax: fp32 scores in, fp16 probabilities out.
// ---------------------------------------------------------------------------
__global__ __launch_bounds__(256)
void softmax_rows(const float* __restrict__ S, __half* __restrict__ P)
{
    const long long row = blockIdx.x;
    const float* p = S + row * (long long)SEQ;
    __half* q = P + row * (long long)SEQ;
    const int tid = threadIdx.x;
    const int lane = tid & 31;
    const int warp = tid >> 5;

    __shared__ float red_max[8];
    __shared__ float red_sum[8];

    float v[8];
    float m = -1e30f;
    #pragma unroll
    for (int i = 0; i < 8; i++) {
        v[i] = p[tid + i * 256];
        m = fmaxf(m, v[i]);
    }
    #pragma unroll
    for (int o = 16; o > 0; o >>= 1) m = fmaxf(m, __shfl_xor_sync(0xffffffffu, m, o));
    if (lane == 0) red_max[warp] = m;
    __syncthreads();
    float mall = red_max[0];
    #pragma unroll
    for (int w = 1; w < 8; w++) mall = fmaxf(mall, red_max[w]);

    float s = 0.0f;
    #pragma unroll
    for (int i = 0; i < 8; i++) {
        v[i] = __expf(v[i] - mall);
        s += v[i];
    }
    #pragma unroll
    for (int o = 16; o > 0; o >>= 1) s += __shfl_xor_sync(0xffffffffu, s, o);
    if (lane == 0) red_sum[warp] = s;
    __syncthreads();
    float sall = 0.0f;
    #pragma unroll
    for (int w = 0; w < 8; w++) sall += red_sum[w];

    const float inv = __frcp_rn(sall);
    #pragma unroll
    for (int i = 0; i < 8; i++) q[tid + i * 256] = __float2half_rn(v[i] * inv);
}

// ---------------------------------------------------------------------------
// Launch
// ---------------------------------------------------------------------------
extern "C" void kernel_launch(void* const* d_in, const int* in_sizes, int n_in,
                              void* d_out, int out_size)
{
    const float* x  = (const float*)d_in[0];
    const float* W1 = (const float*)d_in[1];
    const float* b1 = (const float*)d_in[2];
    const float* W2 = (const float*)d_in[3];
    const float* b2 = (const float*)d_in[4];
    float* out = (float*)d_out;

    __half *pxh, *pW1h, *pW2h, *pVh, *pKh, *pVTh, *pPh;
    float *pS;
    cudaGetSymbolAddress((void**)&pxh,  g_xh);
    cudaGetSymbolAddress((void**)&pW1h, g_W1h);
    cudaGetSymbolAddress((void**)&pW2h, g_W2h);
    cudaGetSymbolAddress((void**)&pVh,  g_Vh);
    cudaGetSymbolAddress((void**)&pKh,  g_Kh);
    cudaGetSymbolAddress((void**)&pVTh, g_VTh);
    cudaGetSymbolAddress((void**)&pPh,  g_Ph);
    cudaGetSymbolAddress((void**)&pS,   g_S);

    const int SMEM_SZ = NSTAGE * STG;  // 98304
    cudaFuncSetAttribute(mm_h16, cudaFuncAttributeMaxDynamicSharedMemorySize, SMEM_SZ);

    const int M_lin = BATCH * SEQ;     // 16384
    const float scale = 1.0f / 32.0f;  // 1/sqrt(1024)

    // 1. fp32 -> fp16 inputs
    f2h<<<2048, 256>>>(x,  pxh,  (long long)M_lin * DIMD / 4);
    f2h<<<512,  256>>>(W1, pW1h, (long long)DIMD * DIMD / 4);
    f2h<<<512,  256>>>(W2, pW2h, (long long)DIMD * DIMD / 4);

    // 2. V = fp16(x @ W1^T + b1);  K = fp16(x @ W2^T + b2)
    mm_h16<<<dim3(DIMD / BN, M_lin / BM, 1), 256, SMEM_SZ>>>(
        pxh, pW1h, b1, pVh, M_lin, DIMD, DIMD, 1.0f, 0, 0, 0, 0);
    mm_h16<<<dim3(DIMD / BN, M_lin / BM, 1), 256, SMEM_SZ>>>(
        pxh, pW2h, b2, pKh, M_lin, DIMD, DIMD, 1.0f, 0, 0, 0, 0);

    // 3. VT = V^T per batch
    transpose_h<<<dim3(DIMD / 32, SEQ / 32, BATCH), dim3(32, 8)>>>(pVh, pVTh);

    // 4. scores[b,k,q] = scale * K[b,k,:] . V[b,q,:]  (fp32 out)
    mm_h16<<<dim3(SEQ / BN, SEQ / BM, BATCH), 256, SMEM_SZ>>>(
        pKh, pVh, nullptr, pS, SEQ, SEQ, DIMD, scale, 1,
        (long long)SEQ * DIMD, (long long)SEQ * DIMD, (long long)SEQ * SEQ);

    // 5. softmax -> fp16 probabilities
    softmax_rows<<<BATCH * SEQ, 256>>>(pS, pPh);

    // 6. out[b,k,d] = P[b,k,:] @ VT[b,d,:]^T  (fp32 out)
    mm_h16<<<dim3(DIMD / BN, SEQ / BM, BATCH), 256, SMEM_SZ>>>(
        pPh, pVTh, nullptr, out, SEQ, DIMD, SEQ, 1.0f, 1,
        (long long)SEQ * SEQ, (long long)SEQ * DIMD, (long long)SEQ * DIMD);
}

// round 4
// speedup vs baseline: 7.3247x; 1.0392x over previous
#include <cuda_runtime.h>
#include <cuda_fp16.h>
#include <cstdint>

#define DIMD  1024
#define BATCH 8
#define SEQ   2048

// ---------------------------------------------------------------------------
// Scratch (static device memory — no allocations)
// ---------------------------------------------------------------------------
__device__ __half g_xh [(size_t)BATCH * SEQ * DIMD];   // x in fp16
__device__ __half g_W1h[(size_t)DIMD * DIMD];
__device__ __half g_W2h[(size_t)DIMD * DIMD];
__device__ __half g_Vh [(size_t)BATCH * SEQ * DIMD];   // V fp16 (== Q)
__device__ __half g_Kh [(size_t)BATCH * SEQ * DIMD];   // K fp16
__device__ __half g_VTh[(size_t)BATCH * SEQ * DIMD];   // V^T fp16 [B,D,S]
__device__ __half g_Sh [(size_t)BATCH * SEQ * SEQ];    // scores / probs fp16

// ---------------------------------------------------------------------------
// Helpers
// ---------------------------------------------------------------------------
__device__ __forceinline__ uint32_t smem_u32(const void* p) {
    return (uint32_t)__cvta_generic_to_shared(p);
}
// SW64 swizzle for 64-byte rows (Swizzle<2,4,3>): bits[5:4] ^= bits[8:7]
__device__ __forceinline__ uint32_t swz64(uint32_t o) { return o ^ ((o >> 3) & 0x30); }

__device__ __forceinline__ void cp_async16(uint32_t dst, const void* src) {
    asm volatile("cp.async.cg.shared.global [%0], [%1], 16;" :: "r"(dst), "l"(src));
}
__device__ __forceinline__ void cp_commit() {
    asm volatile("cp.async.commit_group;" ::: "memory");
}
__device__ __forceinline__ void cp_wait3() {
    asm volatile("cp.async.wait_group 3;" ::: "memory");
}
__device__ __forceinline__ void ldsm_x4(uint32_t* r, uint32_t addr) {
    asm volatile("ldmatrix.sync.aligned.m8n8.x4.shared.b16 {%0,%1,%2,%3}, [%4];"
                 : "=r"(r[0]), "=r"(r[1]), "=r"(r[2]), "=r"(r[3]) : "r"(addr));
}
__device__ __forceinline__ void mma16816(float* c, const uint32_t* a,
                                         uint32_t b0, uint32_t b1) {
    asm volatile("mma.sync.aligned.m16n8k16.row.col.f32.f16.f16.f32 "
                 "{%0,%1,%2,%3}, {%4,%5,%6,%7}, {%8,%9}, {%0,%1,%2,%3};"
                 : "+f"(c[0]), "+f"(c[1]), "+f"(c[2]), "+f"(c[3])
                 : "r"(a[0]), "r"(a[1]), "r"(a[2]), "r"(a[3]), "r"(b0), "r"(b1));
}

// ---------------------------------------------------------------------------
// fp16 tensor-core GEMM: C[M,N] = alpha * A[M,K] @ B[N,K]^T (+bias)  (NT)
// Tile 128x128, K-chunk 32 halfs (64B rows, SW64), 5-stage cp.async pipeline,
// 8 warps, warp tile 64x32.
// mode 0: half out + fp32 bias.  mode 1: float out.  mode 2: half out.
// ---------------------------------------------------------------------------
#define BM 128
#define BN 128
#define BKH 32
#define STG 16384          // (128 + 128) rows * 64 bytes
#define NSTAGE 5

__global__ __launch_bounds__(256, 2)
void mm_h16(const __half* __restrict__ A, const __half* __restrict__ B,
            const float* __restrict__ bias, void* __restrict__ Cout,
            int M, int N, int K, float alpha, int mode,
            long long sA, long long sB, long long sC)
{
    extern __shared__ char smem[];
    const uint32_t sbase = smem_u32(smem);
    const int tid = threadIdx.x;
    const int wid = tid >> 5;
    const int lane = tid & 31;

    const int bz = blockIdx.z;
    A += (long long)bz * sA;
    B += (long long)bz * sB;

    const int tile_m = blockIdx.y * BM;
    const int tile_n = blockIdx.x * BN;
    const int T = K / BKH;

    // --- loader plan: 1024 16B chunks per stage, 4 per thread ---
    // chunk c: c<512 -> A row (c>>2), k-chunk (c&3); else B row ((c-512)>>2)
    const __half* gsrc[4];
    uint32_t sdst[4];
    #pragma unroll
    for (int i = 0; i < 4; i++) {
        int c = tid + i * 256;
        bool isB = c >= 512;
        int r = (isB ? c - 512 : c) >> 2;
        int kc = c & 3;
        gsrc[i] = (isB ? B + (size_t)(tile_n + r) * K
                       : A + (size_t)(tile_m + r) * K) + kc * 8;
        sdst[i] = (isB ? 8192u : 0u) + swz64((uint32_t)(r * 64 + kc * 16));
    }

#define LOAD_STAGE(s, t) do { \
        uint32_t sb_ = sbase + (uint32_t)(s) * STG; \
        _Pragma("unroll") \
        for (int i_ = 0; i_ < 4; i_++) \
            cp_async16(sb_ + sdst[i_], gsrc[i_] + (size_t)(t) * BKH); \
    } while (0)

    // Prefetch 4 stages (each its own commit group)
    #pragma unroll
    for (int p = 0; p < 4; p++) {
        if (p < T) LOAD_STAGE(p, p);
        cp_commit();
    }

    // --- compute plan: warp tile 64x32, precomputed ldmatrix offsets ---
    const int wm = wid & 1;            // 0..1
    const int wn = wid >> 1;           // 0..3
    const int lr = lane & 15;
    const int lcb = (lane >> 4) * 16;  // 0 or 16 bytes

    uint32_t aoff[2][4], boff[2][2];   // [ks][mi], [ks][nb]
    #pragma unroll
    for (int ks = 0; ks < 2; ks++) {
        #pragma unroll
        for (int mi = 0; mi < 4; mi++)
            aoff[ks][mi] = swz64((uint32_t)((wm * 64 + mi * 16 + lr) * 64
                                            + ks * 32 + lcb));
        #pragma unroll
        for (int nb = 0; nb < 2; nb++)
            boff[ks][nb] = 8192u + swz64((uint32_t)((wn * 32 + nb * 16 + lr) * 64
                                                    + ks * 32 + lcb));
    }

    float acc[4][4][4] = {};

    for (int t = 0; t < T; t++) {
        cp_wait3();
        __syncthreads();

        const uint32_t sa = sbase + (uint32_t)(t % NSTAGE) * STG;

        #pragma unroll
        for (int ks = 0; ks < 2; ks++) {
            uint32_t a[4][4], b[2][4];
            #pragma unroll
            for (int mi = 0; mi < 4; mi++) ldsm_x4(a[mi], sa + aoff[ks][mi]);
            #pragma unroll
            for (int nb = 0; nb < 2; nb++) ldsm_x4(b[nb], sa + boff[ks][nb]);
            #pragma unroll
            for (int mi = 0; mi < 4; mi++)
                #pragma unroll
                for (int ni = 0; ni < 4; ni++)
                    mma16816(acc[mi][ni], a[mi],
                             b[ni >> 1][ni & 1], b[ni >> 1][(ni & 1) + 2]);
        }

        if (t + 4 < T) LOAD_STAGE((t + 4) % NSTAGE, t + 4);
        cp_commit();   // empty groups near tail keep wait_group 3 correct
    }

    // --- epilogue ---
    const int er = lane >> 2;
    const int ec = (lane & 3) * 2;

    if (mode == 1) {
        float* C = (float*)Cout + (long long)bz * sC;
        #pragma unroll
        for (int mi = 0; mi < 4; mi++) {
            #pragma unroll
            for (int ni = 0; ni < 4; ni++) {
                int m0 = tile_m + wm * 64 + mi * 16 + er;
                int n0 = tile_n + wn * 32 + ni * 8 + ec;
                float* c = acc[mi][ni];
                *(float2*)(C + (size_t)m0 * N + n0) =
                    make_float2(c[0] * alpha, c[1] * alpha);
                *(float2*)(C + (size_t)(m0 + 8) * N + n0) =
                    make_float2(c[2] * alpha, c[3] * alpha);
            }
        }
    } else {
        __half* C = (__half*)Cout + (long long)bz * sC;
        #pragma unroll
        for (int mi = 0; mi < 4; mi++) {
            #pragma unroll
            for (int ni = 0; ni < 4; ni++) {
                int m0 = tile_m + wm * 64 + mi * 16 + er;
                int n0 = tile_n + wn * 32 + ni * 8 + ec;
                float bx = 0.f, by = 0.f;
                if (mode == 0) { bx = bias[n0]; by = bias[n0 + 1]; }
                float* c = acc[mi][ni];
                *(__half2*)(C + (size_t)m0 * N + n0) =
                    __floats2half2_rn(c[0] * alpha + bx, c[1] * alpha + by);
                *(__half2*)(C + (size_t)(m0 + 8) * N + n0) =
                    __floats2half2_rn(c[2] * alpha + bx, c[3] * alpha + by);
            }
        }
    }
#undef LOAD_STAGE
}

// ---------------------------------------------------------------------------
// fp32 -> fp16 conversion (vectorized)
// ---------------------------------------------------------------------------
__global__ __launch_bounds__(256)
void f2h(const float* __restrict__ in, __half* __restrict__ out, long long n4)
{
    long long i = (long long)blockIdx.x * blockDim.x + threadIdx.x;
    long long stride = (long long)gridDim.x * blockDim.x;
    for (; i < n4; i += stride) {
        float4 v = ((const float4*)in)[i];
        ((__half2*)out)[2 * i + 0] = __floats2half2_rn(v.x, v.y);
        ((__half2*)out)[2 * i + 1] = __floats2half2_rn(v.z, v.w);
    }
}

// ---------------------------------------------------------------------------
// Batched fp16 transpose: [B,S,D] -> [B,D,S]
// ---------------------------------------------------------------------------
__global__ __launch_bounds__(256)
void transpose_h(const __half* __restrict__ in, __half* __restrict__ out)
{
    __shared__ __half t[32][33];
    const int b = blockIdx.z;
    const __half* I = in + (size_t)b * SEQ * DIMD;
    __half* O = out + (size_t)b * SEQ * DIMD;
    const int d0 = blockIdx.x * 32, s0 = blockIdx.y * 32;
    #pragma unroll
    for (int i = threadIdx.y; i < 32; i += 8)
        t[i][threadIdx.x] = I[(size_t)(s0 + i) * DIMD + d0 + threadIdx.x];
    __syncthreads();
    #pragma unroll
    for (int i = threadIdx.y; i < 32; i += 8)
        O[(size_t)(d0 + i) * SEQ + s0 + threadIdx.x] = t[threadIdx.x][i];
}

// ---------------------------------------------------------------------------
// Row softmax over fp16 scores, in place (fp32 math inside).
// ---------------------------------------------------------------------------
__global__ __launch_bounds__(256)
void softmax_rows_h(__half* __restrict__ S)
{
    const long long row = blockIdx.x;
    __half* p = S + row * (long long)SEQ;
    const int tid = threadIdx.x;
    const int lane = tid & 31;
    const int warp = tid >> 5;

    __shared__ float red_max[8];
    __shared__ float red_sum[8];

    // 8 contiguous halfs per thread (16B)
    float v[8];
    {
        uint4 raw = *(const uint4*)(p + tid * 8);
        const __half2* h = (const __half2*)&raw;
        #pragma unroll
        for (int i = 0; i < 4; i++) {
            float2 f = __half22float2(h[i]);
            v[2 * i] = f.x; v[2 * i + 1] = f.y;
        }
    }
    float m = v[0];
    #pragma unroll
    for (int i = 1; i < 8; i++) m = fmaxf(m, v[i]);
    #pragma unroll
    for (int o = 16; o > 0; o >>= 1) m = fmaxf(m, __shfl_xor_sync(0xffffffffu, m, o));
    if (lane == 0) red_max[warp] = m;
    __syncthreads();
    float mall = red_max[0];
    #pragma unroll
    for (int w = 1; w < 8; w++) mall = fmaxf(mall, red_max[w]);

    float s = 0.0f;
    #pragma unroll
    for (int i = 0; i < 8; i++) {
        v[i] = __expf(v[i] - mall);
        s += v[i];
    }
    #pragma unroll
    for (int o = 16; o > 0; o >>= 1) s += __shfl_xor_sync(0xffffffffu, s, o);
    if (lane == 0) red_sum[warp] = s;
    __syncthreads();
    float sall = 0.0f;
    #pragma unroll
    for (int w = 0; w < 8; w++) sall += red_sum[w];

    const float inv = __frcp_rn(sall);
    {
        uint4 raw;
        __half2* h = (__half2*)&raw;
        #pragma unroll
        for (int i = 0; i < 4; i++)
            h[i] = __floats2half2_rn(v[2 * i] * inv, v[2 * i + 1] * inv);
        *(uint4*)(p + tid * 8) = raw;
    }
}

// ---------------------------------------------------------------------------
// Launch
// ---------------------------------------------------------------------------
extern "C" void kernel_launch(void* const* d_in, const int* in_sizes, int n_in,
                              void* d_out, int out_size)
{
    const float* x  = (const float*)d_in[0];
    const float* W1 = (const float*)d_in[1];
    const float* b1 = (const float*)d_in[2];
    const float* W2 = (const float*)d_in[3];
    const float* b2 = (const float*)d_in[4];
    float* out = (float*)d_out;

    __half *pxh, *pW1h, *pW2h, *pVh, *pKh, *pVTh, *pSh;
    cudaGetSymbolAddress((void**)&pxh,  g_xh);
    cudaGetSymbolAddress((void**)&pW1h, g_W1h);
    cudaGetSymbolAddress((void**)&pW2h, g_W2h);
    cudaGetSymbolAddress((void**)&pVh,  g_Vh);
    cudaGetSymbolAddress((void**)&pKh,  g_Kh);
    cudaGetSymbolAddress((void**)&pVTh, g_VTh);
    cudaGetSymbolAddress((void**)&pSh,  g_Sh);

    const int SMEM_SZ = NSTAGE * STG;  // 81920
    cudaFuncSetAttribute(mm_h16, cudaFuncAttributeMaxDynamicSharedMemorySize, SMEM_SZ);

    const int M_lin = BATCH * SEQ;     // 16384
    const float scale = 1.0f / 32.0f;  // 1/sqrt(1024)

    // 1. fp32 -> fp16 inputs
    f2h<<<2048, 256>>>(x,  pxh,  (long long)M_lin * DIMD / 4);
    f2h<<<512,  256>>>(W1, pW1h, (long long)DIMD * DIMD / 4);
    f2h<<<512,  256>>>(W2, pW2h, (long long)DIMD * DIMD / 4);

    // 2. V = fp16(x @ W1^T + b1);  K = fp16(x @ W2^T + b2)
    mm_h16<<<dim3(DIMD / BN, M_lin / BM, 1), 256, SMEM_SZ>>>(
        pxh, pW1h, b1, pVh, M_lin, DIMD, DIMD, 1.0f, 0, 0, 0, 0);
    mm_h16<<<dim3(DIMD / BN, M_lin / BM, 1), 256, SMEM_SZ>>>(
        pxh, pW2h, b2, pKh, M_lin, DIMD, DIMD, 1.0f, 0, 0, 0, 0);

    // 3. VT = V^T per batch
    transpose_h<<<dim3(DIMD / 32, SEQ / 32, BATCH), dim3(32, 8)>>>(pVh, pVTh);

    // 4. scores[b,k,q] = fp16(scale * K[b,k,:] . V[b,q,:])
    mm_h16<<<dim3(SEQ / BN, SEQ / BM, BATCH), 256, SMEM_SZ>>>(
        pKh, pVh, nullptr, pSh, SEQ, SEQ, DIMD, scale, 2,
        (long long)SEQ * DIMD, (long long)SEQ * DIMD, (long long)SEQ * SEQ);

    // 5. softmax in place (fp16)
    softmax_rows_h<<<BATCH * SEQ, 256>>>(pSh);

    // 6. out[b,k,d] = P[b,k,:] @ VT[b,d,:]^T  (fp32 out)
    mm_h16<<<dim3(DIMD / BN, SEQ / BM, BATCH), 256, SMEM_SZ>>>(
        pSh, pVTh, nullptr, out, SEQ, DIMD, SEQ, 1.0f, 1,
        (long long)SEQ * SEQ, (long long)SEQ * DIMD, (long long)SEQ * DIMD);
}